// round 15
// baseline (speedup 1.0000x reference)
#include <cuda_runtime.h>
#include <cuda_fp16.h>
#include <math.h>
#include <stdint.h>

// ---------------- problem constants ------------------------------------------
#define NNODES 32768
#define FDIM   215
#define FPAD   224            // 215 padded to 32
#define HDIM   256
#define TTYPES 8
#define LLAYERS 3
#define NEDGES 524288
#define KMSG   2080           // 8*256 + 8 counts, padded to 32
#define BGRAPH 32
#define MAXN_  1024

// ---------------- cp.async helpers -------------------------------------------
#define CP_ASYNC16(saddr, gptr) \
    asm volatile("cp.async.cg.shared.global [%0], [%1], 16;" :: "r"(saddr), "l"(gptr))
#define CP_COMMIT() asm volatile("cp.async.commit_group;" ::: "memory")
#define CP_WAIT2()  asm volatile("cp.async.wait_group 2;" ::: "memory")
#define CP_WAIT1()  asm volatile("cp.async.wait_group 1;" ::: "memory")
#define CP_WAIT0()  asm volatile("cp.async.wait_group 0;" ::: "memory")

__device__ __forceinline__ uint32_t smem_u32(const void* p) {
    uint32_t a;
    asm("{ .reg .u64 t; cvta.to.shared.u64 t, %1; cvt.u32.u64 %0, t; }" : "=r"(a) : "l"(p));
    return a;
}
__device__ __forceinline__ void mma_f16(float* d, const uint32_t* a, const uint32_t* b) {
    asm volatile(
        "mma.sync.aligned.m16n8k16.row.col.f32.f16.f16.f32 "
        "{%0,%1,%2,%3}, {%4,%5,%6,%7}, {%8,%9}, {%0,%1,%2,%3};"
        : "+f"(d[0]), "+f"(d[1]), "+f"(d[2]), "+f"(d[3])
        : "r"(a[0]), "r"(a[1]), "r"(a[2]), "r"(a[3]), "r"(b[0]), "r"(b[1]));
}

// Tile-ready fp16 layout: panels of 128 rows x 32 k (2048 half2 per chunk),
// element (row,k): half2 index = chunkbase + (row&127)*16 + (((k&31)>>1) ^ ((row&7)*2)).
__device__ __forceinline__ size_t t_idx(int row, int k, int K) {
    return ((size_t)((row >> 7) * (K >> 5) + (k >> 5))) * 2048
         + (size_t)((row & 127) * 16 + ((((k & 31) >> 1)) ^ ((row & 7) * 2)));
}

// ---------------- device scratch ---------------------------------------------
__device__ float   g_h0[NNODES * HDIM];
__device__ float   g_h1[NNODES * HDIM];
__device__ __half2 g_gi[NNODES * 3 * HDIM / 2];         // fp16 row-major
__device__ __half2 g_gh[NNODES * 3 * HDIM / 2];         // fp16 row-major
__device__ float   g_part[BGRAPH * 8 * HDIM];
__device__ __half2 g_Xp [NNODES * (FPAD / 2)];          // tile-ready
__device__ __half2 g_Wpp[HDIM * (FPAD / 2)];            // tile-ready
__device__ __half2 g_Wcat[LLAYERS * HDIM * (KMSG / 2)]; // tile-ready, all layers
__device__ __half2 g_Wih_t[LLAYERS * 3 * HDIM * (HDIM / 2)];
__device__ __half2 g_Whh_t[LLAYERS * 3 * HDIM * (HDIM / 2)];
__device__ __half2 g_S [(size_t)NNODES * (KMSG / 2)];   // tile-ready
__device__ __half2 g_m [NNODES * (HDIM / 2)];           // tile-ready
__device__ __half2 g_ht[NNODES * (HDIM / 2)];           // tile-ready
__device__ int     g_rowstart[NNODES + 1];
__device__ int     g_deg8[NNODES * TTYPES];
__device__ int     g_rs2[NNODES * TTYPES + 1];          // type-segmented CSR offsets
__device__ int     g_cur2[NNODES * TTYPES];
__device__ int     g_srcs[NEDGES];                      // src ids grouped by (dst,type)

// ---------------- CSR build (once per launch) ---------------------------------
__global__ void hist8_kernel(const int* __restrict__ dst, const int* __restrict__ typ,
                             int* __restrict__ deg8) {
    int e = blockIdx.x * 256 + threadIdx.x;
    if (e < NEDGES) atomicAdd(&deg8[dst[e] * TTYPES + typ[e]], 1);
}

// prefix over per-node degree (summed from deg8 inline)
__global__ void scan_kernel(const int* __restrict__ deg8, int* __restrict__ rowstart) {
    __shared__ int part[1024];
    int tid = threadIdx.x;
    int base = tid * 32;
    int local[32];
    int s = 0;
#pragma unroll
    for (int i = 0; i < 32; i++) {
        int d = 0;
#pragma unroll
        for (int t = 0; t < TTYPES; t++) d += deg8[(base + i) * TTYPES + t];
        local[i] = s;
        s += d;
    }
    part[tid] = s;
    __syncthreads();
    for (int off = 1; off < 1024; off <<= 1) {
        int v = (tid >= off) ? part[tid - off] : 0;
        __syncthreads();
        part[tid] += v;
        __syncthreads();
    }
    int prev = (tid > 0) ? part[tid - 1] : 0;
#pragma unroll
    for (int i = 0; i < 32; i++) rowstart[base + i] = prev + local[i];
    if (tid == 1023) rowstart[NNODES] = part[1023];
}

// per-node 8-way offsets: rs2[v*8+t] = rowstart[v] + prefix(deg8[v][0..t))
__global__ void rs2_kernel(const int* __restrict__ rowstart, const int* __restrict__ deg8,
                           int* __restrict__ rs2, int* __restrict__ cur2) {
    int v = blockIdx.x * 256 + threadIdx.x;
    if (v >= NNODES) return;
    int s = rowstart[v];
#pragma unroll
    for (int t = 0; t < TTYPES; t++) {
        rs2[v * TTYPES + t] = s;
        cur2[v * TTYPES + t] = s;
        s += deg8[v * TTYPES + t];
    }
    if (v == 0) rs2[NNODES * TTYPES] = NEDGES;
}

__global__ void scatter2_kernel(const int* __restrict__ src, const int* __restrict__ dst,
                                const int* __restrict__ typ,
                                int* __restrict__ cur2, int* __restrict__ srcs) {
    int e = blockIdx.x * 256 + threadIdx.x;
    if (e < NEDGES) {
        int pos = atomicAdd(&cur2[dst[e] * TTYPES + typ[e]], 1);
        srcs[pos] = src[e];
    }
}

// ---------------- operand prep (all tile-ready fp16) --------------------------
__global__ void pad_x_kernel(const float* __restrict__ X, __half2* __restrict__ Xp) {
    int idx = blockIdx.x * 256 + threadIdx.x;             // NNODES * 112
    int n = idx / (FPAD / 2), c2 = idx % (FPAD / 2);
    int k = c2 * 2;
    float f0 = (k     < FDIM) ? X[(size_t)n * FDIM + k]     : 0.f;
    float f1 = (k + 1 < FDIM) ? X[(size_t)n * FDIM + k + 1] : 0.f;
    Xp[t_idx(n, k, FPAD)] = __floats2half2_rn(f0, f1);
}
__global__ void pad_wp_kernel(const float* __restrict__ Wp, __half2* __restrict__ Wpp) {
    int idx = blockIdx.x * 256 + threadIdx.x;             // HDIM * 112
    int n = idx / (FPAD / 2), c2 = idx % (FPAD / 2);
    int k = c2 * 2;
    float f0 = (k     < FDIM) ? Wp[n * FDIM + k]     : 0.f;
    float f1 = (k + 1 < FDIM) ? Wp[n * FDIM + k + 1] : 0.f;
    Wpp[t_idx(n, k, FPAD)] = __floats2half2_rn(f0, f1);
}
__global__ void cvt_wg_kernel(const float* __restrict__ Wih, const float* __restrict__ Whh,
                              __half2* __restrict__ Wih_t, __half2* __restrict__ Whh_t) {
    int idx = blockIdx.x * 256 + threadIdx.x;             // L * 768 * 128
    const int per_layer = 3 * HDIM * (HDIM / 2);          // 98304
    int l = idx / per_layer, r2 = idx % per_layer;
    int row = r2 / (HDIM / 2), c2 = r2 % (HDIM / 2);
    int k = c2 * 2;
    size_t src = (size_t)l * 3 * HDIM * HDIM + (size_t)row * HDIM + k;
    size_t dst = (size_t)l * per_layer + t_idx(row, k, HDIM);
    Wih_t[dst] = __floats2half2_rn(Wih[src], Wih[src + 1]);
    Whh_t[dst] = __floats2half2_rn(Whh[src], Whh[src + 1]);
}
// All layers: Wcat[l][e, t*H+d] = Wm[l,t,e,d]; Wcat[l][e, 2048+t] = bm[l,t,e]
__global__ void prep_wcat_kernel(const float* __restrict__ Wm,
                                 const float* __restrict__ bm, __half2* __restrict__ W) {
    int idx = blockIdx.x * 256 + threadIdx.x;             // L * HDIM * 1040
    const int per_layer = HDIM * (KMSG / 2);
    int l = idx / per_layer, r2 = idx % per_layer;
    int e = r2 / (KMSG / 2), c2 = r2 % (KMSG / 2);
    int k = c2 * 2;
    const float* Wm_l = Wm + (size_t)l * TTYPES * HDIM * HDIM;
    const float* bm_l = bm + (size_t)l * TTYPES * HDIM;
    float f[2];
#pragma unroll
    for (int j = 0; j < 2; j++) {
        int kk = k + j;
        float v = 0.f;
        if (kk < TTYPES * HDIM) {
            int t = kk >> 8, d = kk & 255;
            v = Wm_l[((size_t)t * HDIM + e) * HDIM + d];
        } else if (kk < TTYPES * HDIM + TTYPES) {
            v = bm_l[(kk - TTYPES * HDIM) * HDIM + e];
        }
        f[j] = v;
    }
    W[(size_t)l * per_layer + t_idx(e, k, KMSG)] = __floats2half2_rn(f[0], f[1]);
}

// ---------------- edge aggregation (type-segmented CSR) ------------------------
__global__ __launch_bounds__(128) void aggregate_kernel(
    const __half2* __restrict__ ht, const int* __restrict__ srcs,
    const int* __restrict__ rs2, __half2* __restrict__ S)
{
    const int v = blockIdx.x;
    const int tid = threadIdx.x;              // handles h cols 2tid, 2tid+1
    const int inner0 = (tid >> 4) * 2048;
    const int innerk = tid & 15;
    int seg_end = rs2[v * TTYPES];            // becomes run start below
#pragma unroll
    for (int t = 0; t < TTYPES; t++) {
        int s = seg_end;
        seg_end = rs2[v * TTYPES + t + 1];
        float2 acc = make_float2(0.f, 0.f);
        for (int pos = s; pos < seg_end; pos++) {
            int src = __ldg(&srcs[pos]);      // uniform across block -> broadcast
            size_t gidx = (size_t)((src >> 7) * 8) * 2048 + inner0
                        + (src & 127) * 16 + (innerk ^ ((src & 7) * 2));
            float2 f = __half22float2(__ldg(&ht[gidx]));
            acc.x += f.x;
            acc.y += f.y;
        }
        S[t_idx(v, t * HDIM + tid * 2, KMSG)] = __floats2half2_rn(acc.x, acc.y);
    }
    if (tid < 16) {                           // cols 2048..2079 (counts + pad)
        int k = TTYPES * HDIM + tid * 2;
        float c0 = 0.f, c1 = 0.f;
        if (tid * 2 < TTYPES)
            c0 = (float)(rs2[v * TTYPES + tid * 2 + 1] - rs2[v * TTYPES + tid * 2]);
        if (tid * 2 + 1 < TTYPES)
            c1 = (float)(rs2[v * TTYPES + tid * 2 + 2] - rs2[v * TTYPES + tid * 2 + 1]);
        S[t_idx(v, k, KMSG)] = __floats2half2_rn(c0, c1);
    }
}

// ---------------- fp16 mma.sync GEMM (1 tile per CTA, 2 static jobs) ----------
// Flattened 1-D grid, br-fast order (R13 best): blockIdx.x < nt0 -> job0 tile
// (long-K, dispatched first), else job1 tile (short-K, backfill).
#define STAGE_BYTES 16384
#define STAGE_H2    4096
#define GEMM_SMEM   (4 * STAGE_BYTES)

__global__ __launch_bounds__(128, 3) void gemm_f16_kernel(
    const __half2* __restrict__ A0, const __half2* __restrict__ B0,
    const float* __restrict__ bias0, float* __restrict__ C0f,
    __half2* __restrict__ C0h, __half2* __restrict__ C0hr,
    int K0, int N0, int nt0,
    const __half2* __restrict__ A1, const __half2* __restrict__ B1,
    const float* __restrict__ bias1, __half2* __restrict__ C1hr,
    int K1, int N1)
{
    extern __shared__ __half2 smh[];
    const int tid  = threadIdx.x;
    const int wid  = tid >> 5;
    const int lane = tid & 31;
    const int gid  = lane >> 2;
    const int tig  = lane & 3;
    const int wm   = wid >> 1;
    const int wn   = wid & 1;
    const uint32_t smb = smem_u32(smh);

    const int t = blockIdx.x;
    const __half2* At; const __half2* Bt; const float* bias;
    float* Cf; __half2* Ch; __half2* Chr; int K, N, br, cb;
    if (t < nt0) {
        At = A0; Bt = B0; bias = bias0; Cf = C0f; Ch = C0h; Chr = C0hr;
        K = K0; N = N0; br = t % 256; cb = t / 256;
    } else {
        int t1 = t - nt0;
        At = A1; Bt = B1; bias = bias1; Cf = (float*)0; Ch = (__half2*)0; Chr = C1hr;
        K = K1; N = N1; br = t1 % 256; cb = t1 / 256;
    }

    const int NC = K >> 5;
    const __half2* Apan = At + (size_t)(br * NC) * 2048;
    const __half2* Bpan = Bt + (size_t)(cb * NC) * 2048;

    float acc[4][8][4];
#pragma unroll
    for (int mt = 0; mt < 4; mt++)
#pragma unroll
        for (int nt = 0; nt < 8; nt++)
#pragma unroll
            for (int v = 0; v < 4; v++) acc[mt][nt][v] = 0.f;

    auto load_chunk = [&](int c) {
        uint32_t base = smb + (c & 3) * STAGE_BYTES;
        const char* ga = (const char*)(Apan + (size_t)c * 2048);
        const char* gb = (const char*)(Bpan + (size_t)c * 2048);
#pragma unroll
        for (int i = 0; i < 4; i++) {
            int off = tid * 16 + i * 2048;
            CP_ASYNC16(base + off, ga + off);
            CP_ASYNC16(base + 8192 + off, gb + off);
        }
        CP_COMMIT();
    };

    load_chunk(0);
    load_chunk(1);
    load_chunk(2);
    for (int c = 0; c < NC; c++) {
        if (c <= NC - 3)      { CP_WAIT2(); }
        else if (c == NC - 2) { CP_WAIT1(); }
        else                  { CP_WAIT0(); }
        __syncthreads();
        if (c + 3 < NC) load_chunk(c + 3);

        const __half2* Asb = smh + (c & 3) * STAGE_H2;
        const __half2* Bsb = Asb + 2048;
        const int swz = gid * 2;
#pragma unroll
        for (int step = 0; step < 2; step++) {
            const int kp0 = (step * 8 + tig) ^ swz;
            const int kp1 = (step * 8 + tig + 4) ^ swz;
            uint32_t af[4][4];
#pragma unroll
            for (int mt = 0; mt < 4; mt++) {
                int r0 = wm * 64 + mt * 16 + gid;
                af[mt][0] = *(const uint32_t*)&Asb[r0 * 16 + kp0];
                af[mt][1] = *(const uint32_t*)&Asb[(r0 + 8) * 16 + kp0];
                af[mt][2] = *(const uint32_t*)&Asb[r0 * 16 + kp1];
                af[mt][3] = *(const uint32_t*)&Asb[(r0 + 8) * 16 + kp1];
            }
            uint32_t bf[8][2];
#pragma unroll
            for (int nt = 0; nt < 8; nt++) {
                int cn = wn * 64 + nt * 8 + gid;
                bf[nt][0] = *(const uint32_t*)&Bsb[cn * 16 + kp0];
                bf[nt][1] = *(const uint32_t*)&Bsb[cn * 16 + kp1];
            }
#pragma unroll
            for (int mt = 0; mt < 4; mt++)
#pragma unroll
                for (int nt = 0; nt < 8; nt++)
                    mma_f16(acc[mt][nt], af[mt], bf[nt]);
        }
    }

    // epilogue
    const int col0 = cb * 128 + wn * 64;
#pragma unroll
    for (int mt = 0; mt < 4; mt++) {
        int rg = br * 128 + wm * 64 + mt * 16 + gid;
#pragma unroll
        for (int nt = 0; nt < 8; nt++) {
            int col = col0 + nt * 8 + tig * 2;
            float b0 = 0.f, b1 = 0.f;
            if (bias) { b0 = __ldg(&bias[col]); b1 = __ldg(&bias[col + 1]); }
            float2 v0 = make_float2(acc[mt][nt][0] + b0, acc[mt][nt][1] + b1);
            float2 v1 = make_float2(acc[mt][nt][2] + b0, acc[mt][nt][3] + b1);
            if (Cf) {
                *reinterpret_cast<float2*>(Cf + (size_t)rg * N + col) = v0;
                *reinterpret_cast<float2*>(Cf + (size_t)(rg + 8) * N + col) = v1;
            }
            if (Ch) {
                Ch[t_idx(rg, col, N)] = __floats2half2_rn(v0.x, v0.y);
                Ch[t_idx(rg + 8, col, N)] = __floats2half2_rn(v1.x, v1.y);
            }
            if (Chr) {
                Chr[((size_t)rg * N + col) >> 1] = __floats2half2_rn(v0.x, v0.y);
                Chr[((size_t)(rg + 8) * N + col) >> 1] = __floats2half2_rn(v1.x, v1.y);
            }
        }
    }
}

// ---------------- GRU elementwise (fp16 gi/gh in; fp32 h; emits fp16 tile) ----
__global__ void gru_kernel(const __half2* __restrict__ gi, const __half2* __restrict__ gh,
                           const float* __restrict__ h, float* __restrict__ hout,
                           __half2* __restrict__ ht) {
    int idx = blockIdx.x * 256 + threadIdx.x;    // NNODES*64 total
    int n = idx >> 6;
    int d4 = (idx & 63) * 4;
    const __half2* gin = gi + (size_t)n * (3 * HDIM / 2);
    const __half2* ghn = gh + (size_t)n * (3 * HDIM / 2);
    int o0 = d4 >> 1;
    float2 ir0 = __half22float2(gin[o0]),                 ir1 = __half22float2(gin[o0 + 1]);
    float2 iz0 = __half22float2(gin[(HDIM >> 1) + o0]),   iz1 = __half22float2(gin[(HDIM >> 1) + o0 + 1]);
    float2 in0 = __half22float2(gin[HDIM + o0]),          in1 = __half22float2(gin[HDIM + o0 + 1]);
    float2 hr0 = __half22float2(ghn[o0]),                 hr1 = __half22float2(ghn[o0 + 1]);
    float2 hz0 = __half22float2(ghn[(HDIM >> 1) + o0]),   hz1 = __half22float2(ghn[(HDIM >> 1) + o0 + 1]);
    float2 hn0 = __half22float2(ghn[HDIM + o0]),          hn1 = __half22float2(ghn[HDIM + o0 + 1]);
    float4 hv = *reinterpret_cast<const float4*>(h + (size_t)n * HDIM + d4);
    float4 o;
#define GRU1(X, IR, HR, IZ, HZ, IN, HN, HV) do { \
        float r = 1.f / (1.f + expf(-((IR) + (HR)))); \
        float z = 1.f / (1.f + expf(-((IZ) + (HZ)))); \
        float nn = tanhf((IN) + r * (HN)); \
        o.X = (1.f - z) * nn + z * (HV); \
    } while (0)
    GRU1(x, ir0.x, hr0.x, iz0.x, hz0.x, in0.x, hn0.x, hv.x);
    GRU1(y, ir0.y, hr0.y, iz0.y, hz0.y, in0.y, hn0.y, hv.y);
    GRU1(z, ir1.x, hr1.x, iz1.x, hz1.x, in1.x, hn1.x, hv.z);
    GRU1(w, ir1.y, hr1.y, iz1.y, hz1.y, in1.y, hn1.y, hv.w);
#undef GRU1
    *reinterpret_cast<float4*>(hout + (size_t)n * HDIM + d4) = o;
    ht[t_idx(n, d4, HDIM)]     = __floats2half2_rn(o.x, o.y);
    ht[t_idx(n, d4 + 2, HDIM)] = __floats2half2_rn(o.z, o.w);
}

// ---------------- readout (two-pass, deterministic) ---------------------------
__global__ void readout_part_kernel(const float* __restrict__ h, float* __restrict__ part) {
    int b = blockIdx.x;
    int c = blockIdx.y;
    int d = threadIdx.x;
    const float* p = h + ((size_t)b * MAXN_ + c * 128) * HDIM + d;
    float s = 0.f;
#pragma unroll 4
    for (int i = 0; i < 128; i++) s += p[(size_t)i * HDIM];
    part[(b * 8 + c) * HDIM + d] = s;
}
__global__ void readout_reduce_kernel(const float* __restrict__ part, float* __restrict__ out) {
    int b = blockIdx.x;
    int d = threadIdx.x;
    float s = 0.f;
#pragma unroll
    for (int c = 0; c < 8; c++) s += part[(b * 8 + c) * HDIM + d];
    out[b * HDIM + d] = s;
}

// ---------------- host orchestration -----------------------------------------
extern "C" void kernel_launch(void* const* d_in, const int* in_sizes, int n_in,
                              void* d_out, int out_size) {
    const float* node_features = (const float*)d_in[0];
    const int*   edge_index    = (const int*)  d_in[1];
    const int*   edge_type     = (const int*)  d_in[2];
    const float* Wp  = (const float*)d_in[3];
    const float* bp  = (const float*)d_in[4];
    const float* Wm  = (const float*)d_in[5];
    const float* bm  = (const float*)d_in[6];
    const float* Wih = (const float*)d_in[7];
    const float* Whh = (const float*)d_in[8];
    const float* bih = (const float*)d_in[9];
    const float* bhh = (const float*)d_in[10];
    float* out = (float*)d_out;

    const int* esrc = edge_index;
    const int* edst = edge_index + NEDGES;

    float *h0, *h1, *part;
    __half2 *gi, *gh, *Xp, *Wpp, *Wcat, *Wih_t, *Whh_t, *S, *m, *ht;
    int *rowstart, *deg8, *rs2, *cur2, *srcs;
    cudaGetSymbolAddress((void**)&h0,    g_h0);
    cudaGetSymbolAddress((void**)&h1,    g_h1);
    cudaGetSymbolAddress((void**)&gi,    g_gi);
    cudaGetSymbolAddress((void**)&gh,    g_gh);
    cudaGetSymbolAddress((void**)&part,  g_part);
    cudaGetSymbolAddress((void**)&Xp,    g_Xp);
    cudaGetSymbolAddress((void**)&Wpp,   g_Wpp);
    cudaGetSymbolAddress((void**)&Wcat,  g_Wcat);
    cudaGetSymbolAddress((void**)&Wih_t, g_Wih_t);
    cudaGetSymbolAddress((void**)&Whh_t, g_Whh_t);
    cudaGetSymbolAddress((void**)&S,     g_S);
    cudaGetSymbolAddress((void**)&m,     g_m);
    cudaGetSymbolAddress((void**)&ht,    g_ht);
    cudaGetSymbolAddress((void**)&rowstart, g_rowstart);
    cudaGetSymbolAddress((void**)&deg8,     g_deg8);
    cudaGetSymbolAddress((void**)&rs2,      g_rs2);
    cudaGetSymbolAddress((void**)&cur2,     g_cur2);
    cudaGetSymbolAddress((void**)&srcs,     g_srcs);

    cudaFuncSetAttribute(gemm_f16_kernel,
                         cudaFuncAttributeMaxDynamicSharedMemorySize, GEMM_SMEM);

    const int per_layer_wg = 3 * HDIM * (HDIM / 2);
    const int per_layer_wc = HDIM * (KMSG / 2);

    // prep (all weight prep + type-segmented CSR; once per launch)
    cudaMemsetAsync(deg8, 0, NNODES * TTYPES * sizeof(int));
    pad_x_kernel<<<(NNODES * (FPAD / 2)) / 256, 256>>>(node_features, Xp);
    pad_wp_kernel<<<(HDIM * (FPAD / 2)) / 256, 256>>>(Wp, Wpp);
    cvt_wg_kernel<<<(LLAYERS * per_layer_wg) / 256, 256>>>(Wih, Whh, Wih_t, Whh_t);
    prep_wcat_kernel<<<(LLAYERS * per_layer_wc) / 256, 256>>>(Wm, bm, Wcat);
    // h0 = Xp @ Wpp^T + bp  (fp32 h0 + fp16 tile ht); 512 tiles, single job
    gemm_f16_kernel<<<512, 128, GEMM_SMEM>>>(
        Xp, Wpp, bp, h0, ht, (__half2*)0, FPAD, HDIM, 512,
        (const __half2*)0, (const __half2*)0, (const float*)0, (__half2*)0, 32, 128);
    hist8_kernel<<<NEDGES / 256, 256>>>(edst, edge_type, deg8);
    scan_kernel<<<1, 1024>>>(deg8, rowstart);
    rs2_kernel<<<NNODES / 256, 256>>>(rowstart, deg8, rs2, cur2);
    scatter2_kernel<<<NEDGES / 256, 256>>>(esrc, edst, edge_type, cur2, srcs);

    float* hc = h0;
    float* hn = h1;
    for (int l = 0; l < LLAYERS; l++) {
        const __half2* Wc_l  = Wcat  + (size_t)l * per_layer_wc;
        const __half2* Wih_l = Wih_t + (size_t)l * per_layer_wg;
        const __half2* Whh_l = Whh_t + (size_t)l * per_layer_wg;
        const float*   bih_l = bih + (size_t)l * 3 * HDIM;
        const float*   bhh_l = bhh + (size_t)l * 3 * HDIM;

        aggregate_kernel<<<NNODES, 128>>>(ht, srcs, rs2, S);
        // merged static launch: tiles [0,512) = msg (K=2080, long, dispatched
        // first, fp16 tile out m), tiles [512,2048) = gh (K=256, fp16 rm out).
        gemm_f16_kernel<<<2048, 128, GEMM_SMEM>>>(
            S, Wc_l, (const float*)0, (float*)0, m, (__half2*)0,
            KMSG, HDIM, 512,
            ht, Whh_l, bhh_l, gh, HDIM, 3 * HDIM);
        // gi = m @ Wih_l^T + bih (1536 tiles, fp16 rm out)
        gemm_f16_kernel<<<1536, 128, GEMM_SMEM>>>(
            m, Wih_l, bih_l, (float*)0, (__half2*)0, gi,
            HDIM, 3 * HDIM, 1536,
            (const __half2*)0, (const __half2*)0, (const float*)0, (__half2*)0, 32, 128);

        gru_kernel<<<(NNODES * 64) / 256, 256>>>(gi, gh, hc, hn, ht);
        float* tmp = hc; hc = hn; hn = tmp;
    }

    readout_part_kernel<<<dim3(BGRAPH, 8), 256>>>(hc, part);
    readout_reduce_kernel<<<BGRAPH, HDIM>>>(part, out);
}

// round 16
// speedup vs baseline: 1.0972x; 1.0972x over previous
#include <cuda_runtime.h>
#include <cuda_fp16.h>
#include <math.h>
#include <stdint.h>

// ---------------- problem constants ------------------------------------------
#define NNODES 32768
#define FDIM   215
#define FPAD   224            // 215 padded to 32
#define HDIM   256
#define TTYPES 8
#define LLAYERS 3
#define NEDGES 524288
#define KMSG   2080           // 8*256 + 8 counts, padded to 32
#define BGRAPH 32
#define MAXN_  1024

// ---------------- cp.async helpers -------------------------------------------
#define CP_ASYNC16(saddr, gptr) \
    asm volatile("cp.async.cg.shared.global [%0], [%1], 16;" :: "r"(saddr), "l"(gptr))
#define CP_COMMIT() asm volatile("cp.async.commit_group;" ::: "memory")
#define CP_WAIT2()  asm volatile("cp.async.wait_group 2;" ::: "memory")
#define CP_WAIT1()  asm volatile("cp.async.wait_group 1;" ::: "memory")
#define CP_WAIT0()  asm volatile("cp.async.wait_group 0;" ::: "memory")

__device__ __forceinline__ uint32_t smem_u32(const void* p) {
    uint32_t a;
    asm("{ .reg .u64 t; cvta.to.shared.u64 t, %1; cvt.u32.u64 %0, t; }" : "=r"(a) : "l"(p));
    return a;
}
__device__ __forceinline__ void mma_f16(float* d, const uint32_t* a, const uint32_t* b) {
    asm volatile(
        "mma.sync.aligned.m16n8k16.row.col.f32.f16.f16.f32 "
        "{%0,%1,%2,%3}, {%4,%5,%6,%7}, {%8,%9}, {%0,%1,%2,%3};"
        : "+f"(d[0]), "+f"(d[1]), "+f"(d[2]), "+f"(d[3])
        : "r"(a[0]), "r"(a[1]), "r"(a[2]), "r"(a[3]), "r"(b[0]), "r"(b[1]));
}

// Tile-ready fp16 layout: panels of 128 rows x 32 k (2048 half2 per chunk),
// element (row,k): half2 index = chunkbase + (row&127)*16 + (((k&31)>>1) ^ ((row&7)*2)).
__device__ __forceinline__ size_t t_idx(int row, int k, int K) {
    return ((size_t)((row >> 7) * (K >> 5) + (k >> 5))) * 2048
         + (size_t)((row & 127) * 16 + ((((k & 31) >> 1)) ^ ((row & 7) * 2)));
}

// ---------------- device scratch ---------------------------------------------
__device__ float   g_h0[NNODES * HDIM];
__device__ float   g_h1[NNODES * HDIM];
__device__ __half2 g_gi[NNODES * 3 * HDIM / 2];         // fp16 row-major
__device__ __half2 g_gh[NNODES * 3 * HDIM / 2];         // fp16 row-major
__device__ float   g_part[BGRAPH * 8 * HDIM];
__device__ __half2 g_Xp [NNODES * (FPAD / 2)];          // tile-ready
__device__ __half2 g_Wpp[HDIM * (FPAD / 2)];            // tile-ready
__device__ __half2 g_Wcat[LLAYERS * HDIM * (KMSG / 2)]; // tile-ready, all layers
__device__ __half2 g_Wih_t[LLAYERS * 3 * HDIM * (HDIM / 2)];
__device__ __half2 g_Whh_t[LLAYERS * 3 * HDIM * (HDIM / 2)];
__device__ __half2 g_S [(size_t)NNODES * (KMSG / 2)];   // tile-ready
__device__ __half2 g_m [NNODES * (HDIM / 2)];           // tile-ready
__device__ __half2 g_ht[NNODES * (HDIM / 2)];           // tile-ready
__device__ int     g_deg[NNODES];
__device__ int     g_rowstart[NNODES + 1];
__device__ int     g_deg8[NNODES * TTYPES];
__device__ int     g_rs2[NNODES * TTYPES + 1];          // type-segmented CSR offsets
__device__ int     g_cur2[NNODES * TTYPES];
__device__ int     g_srcs[NEDGES];                      // src ids grouped by (dst,type)

// ---------------- CSR build (once per launch) ---------------------------------
__global__ void hist_kernel(const int* __restrict__ dst, int* __restrict__ deg) {
    int e = blockIdx.x * 256 + threadIdx.x;
    if (e < NEDGES) atomicAdd(&deg[dst[e]], 1);
}

__global__ void hist8_kernel(const int* __restrict__ dst, const int* __restrict__ typ,
                             int* __restrict__ deg8) {
    int e = blockIdx.x * 256 + threadIdx.x;
    if (e < NEDGES) atomicAdd(&deg8[dst[e] * TTYPES + typ[e]], 1);
}

__global__ void scan_kernel(const int* __restrict__ deg, int* __restrict__ rowstart) {
    __shared__ int part[1024];
    int tid = threadIdx.x;
    int base = tid * 32;
    int local[32];
    int s = 0;
#pragma unroll
    for (int i = 0; i < 32; i++) { local[i] = s; s += deg[base + i]; }
    part[tid] = s;
    __syncthreads();
    for (int off = 1; off < 1024; off <<= 1) {
        int v = (tid >= off) ? part[tid - off] : 0;
        __syncthreads();
        part[tid] += v;
        __syncthreads();
    }
    int prev = (tid > 0) ? part[tid - 1] : 0;
#pragma unroll
    for (int i = 0; i < 32; i++) rowstart[base + i] = prev + local[i];
    if (tid == 1023) rowstart[NNODES] = part[1023];
}

// per-node 8-way offsets: rs2[v*8+t] = rowstart[v] + prefix(deg8[v][0..t))
__global__ void rs2_kernel(const int* __restrict__ rowstart, const int* __restrict__ deg8,
                           int* __restrict__ rs2, int* __restrict__ cur2) {
    int v = blockIdx.x * 256 + threadIdx.x;
    if (v >= NNODES) return;
    int s = rowstart[v];
#pragma unroll
    for (int t = 0; t < TTYPES; t++) {
        rs2[v * TTYPES + t] = s;
        cur2[v * TTYPES + t] = s;
        s += deg8[v * TTYPES + t];
    }
    if (v == 0) rs2[NNODES * TTYPES] = NEDGES;
}

__global__ void scatter2_kernel(const int* __restrict__ src, const int* __restrict__ dst,
                                const int* __restrict__ typ,
                                int* __restrict__ cur2, int* __restrict__ srcs) {
    int e = blockIdx.x * 256 + threadIdx.x;
    if (e < NEDGES) {
        int pos = atomicAdd(&cur2[dst[e] * TTYPES + typ[e]], 1);
        srcs[pos] = src[e];
    }
}

// ---------------- operand prep (all tile-ready fp16) --------------------------
__global__ void pad_x_kernel(const float* __restrict__ X, __half2* __restrict__ Xp) {
    int idx = blockIdx.x * 256 + threadIdx.x;             // NNODES * 112
    int n = idx / (FPAD / 2), c2 = idx % (FPAD / 2);
    int k = c2 * 2;
    float f0 = (k     < FDIM) ? X[(size_t)n * FDIM + k]     : 0.f;
    float f1 = (k + 1 < FDIM) ? X[(size_t)n * FDIM + k + 1] : 0.f;
    Xp[t_idx(n, k, FPAD)] = __floats2half2_rn(f0, f1);
}
__global__ void pad_wp_kernel(const float* __restrict__ Wp, __half2* __restrict__ Wpp) {
    int idx = blockIdx.x * 256 + threadIdx.x;             // HDIM * 112
    int n = idx / (FPAD / 2), c2 = idx % (FPAD / 2);
    int k = c2 * 2;
    float f0 = (k     < FDIM) ? Wp[n * FDIM + k]     : 0.f;
    float f1 = (k + 1 < FDIM) ? Wp[n * FDIM + k + 1] : 0.f;
    Wpp[t_idx(n, k, FPAD)] = __floats2half2_rn(f0, f1);
}
__global__ void cvt_wg_kernel(const float* __restrict__ Wih, const float* __restrict__ Whh,
                              __half2* __restrict__ Wih_t, __half2* __restrict__ Whh_t) {
    int idx = blockIdx.x * 256 + threadIdx.x;             // L * 768 * 128
    const int per_layer = 3 * HDIM * (HDIM / 2);          // 98304
    int l = idx / per_layer, r2 = idx % per_layer;
    int row = r2 / (HDIM / 2), c2 = r2 % (HDIM / 2);
    int k = c2 * 2;
    size_t src = (size_t)l * 3 * HDIM * HDIM + (size_t)row * HDIM + k;
    size_t dst = (size_t)l * per_layer + t_idx(row, k, HDIM);
    Wih_t[dst] = __floats2half2_rn(Wih[src], Wih[src + 1]);
    Whh_t[dst] = __floats2half2_rn(Whh[src], Whh[src + 1]);
}
// All layers: Wcat[l][e, t*H+d] = Wm[l,t,e,d]; Wcat[l][e, 2048+t] = bm[l,t,e]
__global__ void prep_wcat_kernel(const float* __restrict__ Wm,
                                 const float* __restrict__ bm, __half2* __restrict__ W) {
    int idx = blockIdx.x * 256 + threadIdx.x;             // L * HDIM * 1040
    const int per_layer = HDIM * (KMSG / 2);
    int l = idx / per_layer, r2 = idx % per_layer;
    int e = r2 / (KMSG / 2), c2 = r2 % (KMSG / 2);
    int k = c2 * 2;
    const float* Wm_l = Wm + (size_t)l * TTYPES * HDIM * HDIM;
    const float* bm_l = bm + (size_t)l * TTYPES * HDIM;
    float f[2];
#pragma unroll
    for (int j = 0; j < 2; j++) {
        int kk = k + j;
        float v = 0.f;
        if (kk < TTYPES * HDIM) {
            int t = kk >> 8, d = kk & 255;
            v = Wm_l[((size_t)t * HDIM + e) * HDIM + d];
        } else if (kk < TTYPES * HDIM + TTYPES) {
            v = bm_l[(kk - TTYPES * HDIM) * HDIM + e];
        }
        f[j] = v;
    }
    W[(size_t)l * per_layer + t_idx(e, k, KMSG)] = __floats2half2_rn(f[0], f[1]);
}

// ---------------- edge aggregation (type-segmented CSR) ------------------------
// No smem, no sync, no sort: per type, linear run of srcs[]; register acc.
__global__ __launch_bounds__(128) void aggregate_kernel(
    const __half2* __restrict__ ht, const int* __restrict__ srcs,
    const int* __restrict__ rs2, __half2* __restrict__ S)
{
    const int v = blockIdx.x;
    const int tid = threadIdx.x;              // handles h cols 2tid, 2tid+1
    const int inner0 = (tid >> 4) * 2048;
    const int innerk = tid & 15;
    int seg_end = rs2[v * TTYPES];            // becomes run start below
#pragma unroll
    for (int t = 0; t < TTYPES; t++) {
        int s = seg_end;
        seg_end = rs2[v * TTYPES + t + 1];
        float2 acc = make_float2(0.f, 0.f);
        for (int pos = s; pos < seg_end; pos++) {
            int src = __ldg(&srcs[pos]);      // uniform across block -> broadcast
            size_t gidx = (size_t)((src >> 7) * 8) * 2048 + inner0
                        + (src & 127) * 16 + (innerk ^ ((src & 7) * 2));
            float2 f = __half22float2(__ldg(&ht[gidx]));
            acc.x += f.x;
            acc.y += f.y;
        }
        S[t_idx(v, t * HDIM + tid * 2, KMSG)] = __floats2half2_rn(acc.x, acc.y);
    }
    if (tid < 16) {                           // cols 2048..2079 (counts + pad)
        int k = TTYPES * HDIM + tid * 2;
        float c0 = 0.f, c1 = 0.f;
        if (tid * 2 < TTYPES)
            c0 = (float)(rs2[v * TTYPES + tid * 2 + 1] - rs2[v * TTYPES + tid * 2]);
        if (tid * 2 + 1 < TTYPES)
            c1 = (float)(rs2[v * TTYPES + tid * 2 + 2] - rs2[v * TTYPES + tid * 2 + 1]);
        S[t_idx(v, k, KMSG)] = __floats2half2_rn(c0, c1);
    }
}

// ---------------- fp16 mma.sync GEMM (1 tile per CTA, 2 static jobs) ----------
#define STAGE_BYTES 16384
#define STAGE_H2    4096
#define GEMM_SMEM   (4 * STAGE_BYTES)

__global__ __launch_bounds__(128, 3) void gemm_f16_kernel(
    const __half2* __restrict__ A0, const __half2* __restrict__ B0,
    const float* __restrict__ bias0, float* __restrict__ C0f,
    __half2* __restrict__ C0h, __half2* __restrict__ C0hr,
    int K0, int N0, int nt0,
    const __half2* __restrict__ A1, const __half2* __restrict__ B1,
    const float* __restrict__ bias1, __half2* __restrict__ C1hr,
    int K1, int N1)
{
    extern __shared__ __half2 smh[];
    const int tid  = threadIdx.x;
    const int wid  = tid >> 5;
    const int lane = tid & 31;
    const int gid  = lane >> 2;
    const int tig  = lane & 3;
    const int wm   = wid >> 1;
    const int wn   = wid & 1;
    const uint32_t smb = smem_u32(smh);

    const int t = blockIdx.x;
    const __half2* At; const __half2* Bt; const float* bias;
    float* Cf; __half2* Ch; __half2* Chr; int K, N, br, cb;
    if (t < nt0) {
        At = A0; Bt = B0; bias = bias0; Cf = C0f; Ch = C0h; Chr = C0hr;
        K = K0; N = N0; br = t % 256; cb = t / 256;
    } else {
        int t1 = t - nt0;
        At = A1; Bt = B1; bias = bias1; Cf = (float*)0; Ch = (__half2*)0; Chr = C1hr;
        K = K1; N = N1; br = t1 % 256; cb = t1 / 256;
    }

    const int NC = K >> 5;
    const __half2* Apan = At + (size_t)(br * NC) * 2048;
    const __half2* Bpan = Bt + (size_t)(cb * NC) * 2048;

    float acc[4][8][4];
#pragma unroll
    for (int mt = 0; mt < 4; mt++)
#pragma unroll
        for (int nt = 0; nt < 8; nt++)
#pragma unroll
            for (int v = 0; v < 4; v++) acc[mt][nt][v] = 0.f;

    auto load_chunk = [&](int c) {
        uint32_t base = smb + (c & 3) * STAGE_BYTES;
        const char* ga = (const char*)(Apan + (size_t)c * 2048);
        const char* gb = (const char*)(Bpan + (size_t)c * 2048);
#pragma unroll
        for (int i = 0; i < 4; i++) {
            int off = tid * 16 + i * 2048;
            CP_ASYNC16(base + off, ga + off);
            CP_ASYNC16(base + 8192 + off, gb + off);
        }
        CP_COMMIT();
    };

    load_chunk(0);
    load_chunk(1);
    load_chunk(2);
    for (int c = 0; c < NC; c++) {
        if (c <= NC - 3)      { CP_WAIT2(); }
        else if (c == NC - 2) { CP_WAIT1(); }
        else                  { CP_WAIT0(); }
        __syncthreads();
        if (c + 3 < NC) load_chunk(c + 3);

        const __half2* Asb = smh + (c & 3) * STAGE_H2;
        const __half2* Bsb = Asb + 2048;
        const int swz = gid * 2;
#pragma unroll
        for (int step = 0; step < 2; step++) {
            const int kp0 = (step * 8 + tig) ^ swz;
            const int kp1 = (step * 8 + tig + 4) ^ swz;
            uint32_t af[4][4];
#pragma unroll
            for (int mt = 0; mt < 4; mt++) {
                int r0 = wm * 64 + mt * 16 + gid;
                af[mt][0] = *(const uint32_t*)&Asb[r0 * 16 + kp0];
                af[mt][1] = *(const uint32_t*)&Asb[(r0 + 8) * 16 + kp0];
                af[mt][2] = *(const uint32_t*)&Asb[r0 * 16 + kp1];
                af[mt][3] = *(const uint32_t*)&Asb[(r0 + 8) * 16 + kp1];
            }
            uint32_t bf[8][2];
#pragma unroll
            for (int nt = 0; nt < 8; nt++) {
                int cn = wn * 64 + nt * 8 + gid;
                bf[nt][0] = *(const uint32_t*)&Bsb[cn * 16 + kp0];
                bf[nt][1] = *(const uint32_t*)&Bsb[cn * 16 + kp1];
            }
#pragma unroll
            for (int mt = 0; mt < 4; mt++)
#pragma unroll
                for (int nt = 0; nt < 8; nt++)
                    mma_f16(acc[mt][nt], af[mt], bf[nt]);
        }
    }

    // epilogue
    const int col0 = cb * 128 + wn * 64;
#pragma unroll
    for (int mt = 0; mt < 4; mt++) {
        int rg = br * 128 + wm * 64 + mt * 16 + gid;
#pragma unroll
        for (int nt = 0; nt < 8; nt++) {
            int col = col0 + nt * 8 + tig * 2;
            float b0 = 0.f, b1 = 0.f;
            if (bias) { b0 = __ldg(&bias[col]); b1 = __ldg(&bias[col + 1]); }
            float2 v0 = make_float2(acc[mt][nt][0] + b0, acc[mt][nt][1] + b1);
            float2 v1 = make_float2(acc[mt][nt][2] + b0, acc[mt][nt][3] + b1);
            if (Cf) {
                *reinterpret_cast<float2*>(Cf + (size_t)rg * N + col) = v0;
                *reinterpret_cast<float2*>(Cf + (size_t)(rg + 8) * N + col) = v1;
            }
            if (Ch) {
                Ch[t_idx(rg, col, N)] = __floats2half2_rn(v0.x, v0.y);
                Ch[t_idx(rg + 8, col, N)] = __floats2half2_rn(v1.x, v1.y);
            }
            if (Chr) {
                Chr[((size_t)rg * N + col) >> 1] = __floats2half2_rn(v0.x, v0.y);
                Chr[((size_t)(rg + 8) * N + col) >> 1] = __floats2half2_rn(v1.x, v1.y);
            }
        }
    }
}

// ---------------- GRU elementwise (fp16 gi/gh in; fp32 h; emits fp16 tile) ----
__global__ void gru_kernel(const __half2* __restrict__ gi, const __half2* __restrict__ gh,
                           const float* __restrict__ h, float* __restrict__ hout,
                           __half2* __restrict__ ht) {
    int idx = blockIdx.x * 256 + threadIdx.x;    // NNODES*64 total
    int n = idx >> 6;
    int d4 = (idx & 63) * 4;
    const __half2* gin = gi + (size_t)n * (3 * HDIM / 2);
    const __half2* ghn = gh + (size_t)n * (3 * HDIM / 2);
    int o0 = d4 >> 1;
    float2 ir0 = __half22float2(gin[o0]),                 ir1 = __half22float2(gin[o0 + 1]);
    float2 iz0 = __half22float2(gin[(HDIM >> 1) + o0]),   iz1 = __half22float2(gin[(HDIM >> 1) + o0 + 1]);
    float2 in0 = __half22float2(gin[HDIM + o0]),          in1 = __half22float2(gin[HDIM + o0 + 1]);
    float2 hr0 = __half22float2(ghn[o0]),                 hr1 = __half22float2(ghn[o0 + 1]);
    float2 hz0 = __half22float2(ghn[(HDIM >> 1) + o0]),   hz1 = __half22float2(ghn[(HDIM >> 1) + o0 + 1]);
    float2 hn0 = __half22float2(ghn[HDIM + o0]),          hn1 = __half22float2(ghn[HDIM + o0 + 1]);
    float4 hv = *reinterpret_cast<const float4*>(h + (size_t)n * HDIM + d4);
    float4 o;
#define GRU1(X, IR, HR, IZ, HZ, IN, HN, HV) do { \
        float r = 1.f / (1.f + expf(-((IR) + (HR)))); \
        float z = 1.f / (1.f + expf(-((IZ) + (HZ)))); \
        float nn = tanhf((IN) + r * (HN)); \
        o.X = (1.f - z) * nn + z * (HV); \
    } while (0)
    GRU1(x, ir0.x, hr0.x, iz0.x, hz0.x, in0.x, hn0.x, hv.x);
    GRU1(y, ir0.y, hr0.y, iz0.y, hz0.y, in0.y, hn0.y, hv.y);
    GRU1(z, ir1.x, hr1.x, iz1.x, hz1.x, in1.x, hn1.x, hv.z);
    GRU1(w, ir1.y, hr1.y, iz1.y, hz1.y, in1.y, hn1.y, hv.w);
#undef GRU1
    *reinterpret_cast<float4*>(hout + (size_t)n * HDIM + d4) = o;
    ht[t_idx(n, d4, HDIM)]     = __floats2half2_rn(o.x, o.y);
    ht[t_idx(n, d4 + 2, HDIM)] = __floats2half2_rn(o.z, o.w);
}

// ---------------- readout (two-pass, deterministic) ---------------------------
__global__ void readout_part_kernel(const float* __restrict__ h, float* __restrict__ part) {
    int b = blockIdx.x;
    int c = blockIdx.y;
    int d = threadIdx.x;
    const float* p = h + ((size_t)b * MAXN_ + c * 128) * HDIM + d;
    float s = 0.f;
#pragma unroll 4
    for (int i = 0; i < 128; i++) s += p[(size_t)i * HDIM];
    part[(b * 8 + c) * HDIM + d] = s;
}
__global__ void readout_reduce_kernel(const float* __restrict__ part, float* __restrict__ out) {
    int b = blockIdx.x;
    int d = threadIdx.x;
    float s = 0.f;
#pragma unroll
    for (int c = 0; c < 8; c++) s += part[(b * 8 + c) * HDIM + d];
    out[b * HDIM + d] = s;
}

// ---------------- host orchestration -----------------------------------------
extern "C" void kernel_launch(void* const* d_in, const int* in_sizes, int n_in,
                              void* d_out, int out_size) {
    const float* node_features = (const float*)d_in[0];
    const int*   edge_index    = (const int*)  d_in[1];
    const int*   edge_type     = (const int*)  d_in[2];
    const float* Wp  = (const float*)d_in[3];
    const float* bp  = (const float*)d_in[4];
    const float* Wm  = (const float*)d_in[5];
    const float* bm  = (const float*)d_in[6];
    const float* Wih = (const float*)d_in[7];
    const float* Whh = (const float*)d_in[8];
    const float* bih = (const float*)d_in[9];
    const float* bhh = (const float*)d_in[10];
    float* out = (float*)d_out;

    const int* esrc = edge_index;
    const int* edst = edge_index + NEDGES;

    float *h0, *h1, *part;
    __half2 *gi, *gh, *Xp, *Wpp, *Wcat, *Wih_t, *Whh_t, *S, *m, *ht;
    int *deg, *rowstart, *deg8, *rs2, *cur2, *srcs;
    cudaGetSymbolAddress((void**)&h0,    g_h0);
    cudaGetSymbolAddress((void**)&h1,    g_h1);
    cudaGetSymbolAddress((void**)&gi,    g_gi);
    cudaGetSymbolAddress((void**)&gh,    g_gh);
    cudaGetSymbolAddress((void**)&part,  g_part);
    cudaGetSymbolAddress((void**)&Xp,    g_Xp);
    cudaGetSymbolAddress((void**)&Wpp,   g_Wpp);
    cudaGetSymbolAddress((void**)&Wcat,  g_Wcat);
    cudaGetSymbolAddress((void**)&Wih_t, g_Wih_t);
    cudaGetSymbolAddress((void**)&Whh_t, g_Whh_t);
    cudaGetSymbolAddress((void**)&S,     g_S);
    cudaGetSymbolAddress((void**)&m,     g_m);
    cudaGetSymbolAddress((void**)&ht,    g_ht);
    cudaGetSymbolAddress((void**)&deg,      g_deg);
    cudaGetSymbolAddress((void**)&rowstart, g_rowstart);
    cudaGetSymbolAddress((void**)&deg8,     g_deg8);
    cudaGetSymbolAddress((void**)&rs2,      g_rs2);
    cudaGetSymbolAddress((void**)&cur2,     g_cur2);
    cudaGetSymbolAddress((void**)&srcs,     g_srcs);

    cudaFuncSetAttribute(gemm_f16_kernel,
                         cudaFuncAttributeMaxDynamicSharedMemorySize, GEMM_SMEM);

    const int per_layer_wg = 3 * HDIM * (HDIM / 2);
    const int per_layer_wc = HDIM * (KMSG / 2);

    // prep (all weight prep + type-segmented CSR; once per launch)
    cudaMemsetAsync(deg, 0, NNODES * sizeof(int));
    cudaMemsetAsync(deg8, 0, NNODES * TTYPES * sizeof(int));
    pad_x_kernel<<<(NNODES * (FPAD / 2)) / 256, 256>>>(node_features, Xp);
    pad_wp_kernel<<<(HDIM * (FPAD / 2)) / 256, 256>>>(Wp, Wpp);
    cvt_wg_kernel<<<(LLAYERS * per_layer_wg) / 256, 256>>>(Wih, Whh, Wih_t, Whh_t);
    prep_wcat_kernel<<<(LLAYERS * per_layer_wc) / 256, 256>>>(Wm, bm, Wcat);
    // h0 = Xp @ Wpp^T + bp  (fp32 h0 + fp16 tile ht); 512 tiles, single job
    gemm_f16_kernel<<<512, 128, GEMM_SMEM>>>(
        Xp, Wpp, bp, h0, ht, (__half2*)0, FPAD, HDIM, 512,
        (const __half2*)0, (const __half2*)0, (const float*)0, (__half2*)0, 32, 128);
    hist_kernel<<<NEDGES / 256, 256>>>(edst, deg);
    hist8_kernel<<<NEDGES / 256, 256>>>(edst, edge_type, deg8);
    scan_kernel<<<1, 1024>>>(deg, rowstart);
    rs2_kernel<<<NNODES / 256, 256>>>(rowstart, deg8, rs2, cur2);
    scatter2_kernel<<<NEDGES / 256, 256>>>(esrc, edst, edge_type, cur2, srcs);

    float* hc = h0;
    float* hn = h1;
    for (int l = 0; l < LLAYERS; l++) {
        const __half2* Wc_l  = Wcat  + (size_t)l * per_layer_wc;
        const __half2* Wih_l = Wih_t + (size_t)l * per_layer_wg;
        const __half2* Whh_l = Whh_t + (size_t)l * per_layer_wg;
        const float*   bih_l = bih + (size_t)l * 3 * HDIM;
        const float*   bhh_l = bhh + (size_t)l * 3 * HDIM;

        aggregate_kernel<<<NNODES, 128>>>(ht, srcs, rs2, S);
        // merged static launch: tiles [0,512) = msg (K=2080, long, dispatched
        // first, fp16 tile out m), tiles [512,2048) = gh (K=256, fp16 rm out).
        gemm_f16_kernel<<<2048, 128, GEMM_SMEM>>>(
            S, Wc_l, (const float*)0, (float*)0, m, (__half2*)0,
            KMSG, HDIM, 512,
            ht, Whh_l, bhh_l, gh, HDIM, 3 * HDIM);
        // gi = m @ Wih_l^T + bih (1536 tiles, fp16 rm out)
        gemm_f16_kernel<<<1536, 128, GEMM_SMEM>>>(
            m, Wih_l, bih_l, (float*)0, (__half2*)0, gi,
            HDIM, 3 * HDIM, 1536,
            (const __half2*)0, (const __half2*)0, (const float*)0, (__half2*)0, 32, 128);

        gru_kernel<<<(NNODES * 64) / 256, 256>>>(gi, gh, hc, hn, ht);
        float* tmp = hc; hc = hn; hn = tmp;
    }

    readout_part_kernel<<<dim3(BGRAPH, 8), 256>>>(hc, part);
    readout_reduce_kernel<<<BGRAPH, HDIM>>>(part, out);
}

// round 17
// speedup vs baseline: 1.1327x; 1.0324x over previous
#include <cuda_runtime.h>
#include <cuda_fp16.h>
#include <math.h>
#include <stdint.h>

// ---------------- problem constants ------------------------------------------
#define NNODES 32768
#define FDIM   215
#define FPAD   224            // 215 padded to 32
#define HDIM   256
#define TTYPES 8
#define LLAYERS 3
#define NEDGES 524288
#define KMSG   2080           // 8*256 + 8 counts, padded to 32
#define BGRAPH 32
#define MAXN_  1024

// ---------------- cp.async helpers -------------------------------------------
#define CP_ASYNC16(saddr, gptr) \
    asm volatile("cp.async.cg.shared.global [%0], [%1], 16;" :: "r"(saddr), "l"(gptr))
#define CP_COMMIT() asm volatile("cp.async.commit_group;" ::: "memory")
#define CP_WAIT2()  asm volatile("cp.async.wait_group 2;" ::: "memory")
#define CP_WAIT1()  asm volatile("cp.async.wait_group 1;" ::: "memory")
#define CP_WAIT0()  asm volatile("cp.async.wait_group 0;" ::: "memory")

__device__ __forceinline__ uint32_t smem_u32(const void* p) {
    uint32_t a;
    asm("{ .reg .u64 t; cvta.to.shared.u64 t, %1; cvt.u32.u64 %0, t; }" : "=r"(a) : "l"(p));
    return a;
}
__device__ __forceinline__ void mma_f16(float* d, const uint32_t* a, const uint32_t* b) {
    asm volatile(
        "mma.sync.aligned.m16n8k16.row.col.f32.f16.f16.f32 "
        "{%0,%1,%2,%3}, {%4,%5,%6,%7}, {%8,%9}, {%0,%1,%2,%3};"
        : "+f"(d[0]), "+f"(d[1]), "+f"(d[2]), "+f"(d[3])
        : "r"(a[0]), "r"(a[1]), "r"(a[2]), "r"(a[3]), "r"(b[0]), "r"(b[1]));
}

// Tile-ready fp16 layout: panels of 128 rows x 32 k (2048 half2 per chunk),
// element (row,k): half2 index = chunkbase + (row&127)*16 + (((k&31)>>1) ^ ((row&7)*2)).
__device__ __forceinline__ size_t t_idx(int row, int k, int K) {
    return ((size_t)((row >> 7) * (K >> 5) + (k >> 5))) * 2048
         + (size_t)((row & 127) * 16 + ((((k & 31) >> 1)) ^ ((row & 7) * 2)));
}

// ---------------- device scratch ---------------------------------------------
__device__ __half2 g_gi[NNODES * 3 * HDIM / 2];         // fp16 row-major
__device__ __half2 g_gh[NNODES * 3 * HDIM / 2];         // fp16 row-major
__device__ float   g_part[BGRAPH * 8 * HDIM];
__device__ __half2 g_Xp [NNODES * (FPAD / 2)];          // tile-ready
__device__ __half2 g_Wpp[HDIM * (FPAD / 2)];            // tile-ready
__device__ __half2 g_Wcat[LLAYERS * HDIM * (KMSG / 2)]; // tile-ready, all layers
__device__ __half2 g_Wih_t[LLAYERS * 3 * HDIM * (HDIM / 2)];
__device__ __half2 g_Whh_t[LLAYERS * 3 * HDIM * (HDIM / 2)];
__device__ __half2 g_S [(size_t)NNODES * (KMSG / 2)];   // tile-ready
__device__ __half2 g_m [NNODES * (HDIM / 2)];           // tile-ready
__device__ __half2 g_ht[NNODES * (HDIM / 2)];           // tile-ready (sole h carrier)
__device__ int     g_deg[NNODES];
__device__ int     g_rowstart[NNODES + 1];
__device__ int     g_deg8[NNODES * TTYPES];
__device__ int     g_rs2[NNODES * TTYPES + 1];          // type-segmented CSR offsets
__device__ int     g_cur2[NNODES * TTYPES];
__device__ int     g_srcs[NEDGES];                      // src ids grouped by (dst,type)

// ---------------- CSR build (once per launch) ---------------------------------
// merged: per-node degree + per-(node,type) degree in one edge pass
__global__ void hist_both_kernel(const int* __restrict__ dst, const int* __restrict__ typ,
                                 int* __restrict__ deg, int* __restrict__ deg8) {
    int e = blockIdx.x * 256 + threadIdx.x;
    if (e < NEDGES) {
        int d = dst[e];
        atomicAdd(&deg[d], 1);
        atomicAdd(&deg8[d * TTYPES + typ[e]], 1);
    }
}

__global__ void scan_kernel(const int* __restrict__ deg, int* __restrict__ rowstart) {
    __shared__ int part[1024];
    int tid = threadIdx.x;
    int base = tid * 32;
    int local[32];
    int s = 0;
#pragma unroll
    for (int i = 0; i < 32; i++) { local[i] = s; s += deg[base + i]; }
    part[tid] = s;
    __syncthreads();
    for (int off = 1; off < 1024; off <<= 1) {
        int v = (tid >= off) ? part[tid - off] : 0;
        __syncthreads();
        part[tid] += v;
        __syncthreads();
    }
    int prev = (tid > 0) ? part[tid - 1] : 0;
#pragma unroll
    for (int i = 0; i < 32; i++) rowstart[base + i] = prev + local[i];
    if (tid == 1023) rowstart[NNODES] = part[1023];
}

// per-node 8-way offsets: rs2[v*8+t] = rowstart[v] + prefix(deg8[v][0..t))
__global__ void rs2_kernel(const int* __restrict__ rowstart, const int* __restrict__ deg8,
                           int* __restrict__ rs2, int* __restrict__ cur2) {
    int v = blockIdx.x * 256 + threadIdx.x;
    if (v >= NNODES) return;
    int s = rowstart[v];
#pragma unroll
    for (int t = 0; t < TTYPES; t++) {
        rs2[v * TTYPES + t] = s;
        cur2[v * TTYPES + t] = s;
        s += deg8[v * TTYPES + t];
    }
    if (v == 0) rs2[NNODES * TTYPES] = NEDGES;
}

__global__ void scatter2_kernel(const int* __restrict__ src, const int* __restrict__ dst,
                                const int* __restrict__ typ,
                                int* __restrict__ cur2, int* __restrict__ srcs) {
    int e = blockIdx.x * 256 + threadIdx.x;
    if (e < NEDGES) {
        int pos = atomicAdd(&cur2[dst[e] * TTYPES + typ[e]], 1);
        srcs[pos] = src[e];
    }
}

// ---------------- merged operand prep (all tile-ready fp16) -------------------
#define NPX (NNODES * (FPAD / 2))                     // pad_x
#define NPW (HDIM * (FPAD / 2))                       // pad_wp
#define NWG (LLAYERS * 3 * HDIM * (HDIM / 2))         // cvt_wg
#define NWC (LLAYERS * HDIM * (KMSG / 2))             // prep_wcat
#define NPREP (NPX + NPW + NWG + NWC)

__global__ void prep_all_kernel(
    const float* __restrict__ X, const float* __restrict__ Wp,
    const float* __restrict__ Wih, const float* __restrict__ Whh,
    const float* __restrict__ Wm, const float* __restrict__ bm,
    __half2* __restrict__ Xp, __half2* __restrict__ Wpp,
    __half2* __restrict__ Wih_t, __half2* __restrict__ Whh_t,
    __half2* __restrict__ W)
{
    int idx = blockIdx.x * 256 + threadIdx.x;
    if (idx < NPX) {
        int n = idx / (FPAD / 2), c2 = idx % (FPAD / 2);
        int k = c2 * 2;
        float f0 = (k     < FDIM) ? X[(size_t)n * FDIM + k]     : 0.f;
        float f1 = (k + 1 < FDIM) ? X[(size_t)n * FDIM + k + 1] : 0.f;
        Xp[t_idx(n, k, FPAD)] = __floats2half2_rn(f0, f1);
    } else if (idx < NPX + NPW) {
        int i = idx - NPX;
        int n = i / (FPAD / 2), c2 = i % (FPAD / 2);
        int k = c2 * 2;
        float f0 = (k     < FDIM) ? Wp[n * FDIM + k]     : 0.f;
        float f1 = (k + 1 < FDIM) ? Wp[n * FDIM + k + 1] : 0.f;
        Wpp[t_idx(n, k, FPAD)] = __floats2half2_rn(f0, f1);
    } else if (idx < NPX + NPW + NWG) {
        int i = idx - NPX - NPW;
        const int per_layer = 3 * HDIM * (HDIM / 2);
        int l = i / per_layer, r2 = i % per_layer;
        int row = r2 / (HDIM / 2), c2 = r2 % (HDIM / 2);
        int k = c2 * 2;
        size_t src = (size_t)l * 3 * HDIM * HDIM + (size_t)row * HDIM + k;
        size_t dst = (size_t)l * per_layer + t_idx(row, k, HDIM);
        Wih_t[dst] = __floats2half2_rn(Wih[src], Wih[src + 1]);
        Whh_t[dst] = __floats2half2_rn(Whh[src], Whh[src + 1]);
    } else if (idx < NPREP) {
        int i = idx - NPX - NPW - NWG;
        const int per_layer = HDIM * (KMSG / 2);
        int l = i / per_layer, r2 = i % per_layer;
        int e = r2 / (KMSG / 2), c2 = r2 % (KMSG / 2);
        int k = c2 * 2;
        const float* Wm_l = Wm + (size_t)l * TTYPES * HDIM * HDIM;
        const float* bm_l = bm + (size_t)l * TTYPES * HDIM;
        float f[2];
#pragma unroll
        for (int j = 0; j < 2; j++) {
            int kk = k + j;
            float v = 0.f;
            if (kk < TTYPES * HDIM) {
                int t = kk >> 8, d = kk & 255;
                v = Wm_l[((size_t)t * HDIM + e) * HDIM + d];
            } else if (kk < TTYPES * HDIM + TTYPES) {
                v = bm_l[(kk - TTYPES * HDIM) * HDIM + e];
            }
            f[j] = v;
        }
        W[(size_t)l * per_layer + t_idx(e, k, KMSG)] = __floats2half2_rn(f[0], f[1]);
    }
}

// ---------------- edge aggregation (type-segmented CSR) ------------------------
__global__ __launch_bounds__(128) void aggregate_kernel(
    const __half2* __restrict__ ht, const int* __restrict__ srcs,
    const int* __restrict__ rs2, __half2* __restrict__ S)
{
    const int v = blockIdx.x;
    const int tid = threadIdx.x;              // handles h cols 2tid, 2tid+1
    const int inner0 = (tid >> 4) * 2048;
    const int innerk = tid & 15;
    int seg_end = rs2[v * TTYPES];            // becomes run start below
#pragma unroll
    for (int t = 0; t < TTYPES; t++) {
        int s = seg_end;
        seg_end = rs2[v * TTYPES + t + 1];
        float2 acc = make_float2(0.f, 0.f);
        for (int pos = s; pos < seg_end; pos++) {
            int src = __ldg(&srcs[pos]);      // uniform across block -> broadcast
            size_t gidx = (size_t)((src >> 7) * 8) * 2048 + inner0
                        + (src & 127) * 16 + (innerk ^ ((src & 7) * 2));
            float2 f = __half22float2(__ldg(&ht[gidx]));
            acc.x += f.x;
            acc.y += f.y;
        }
        S[t_idx(v, t * HDIM + tid * 2, KMSG)] = __floats2half2_rn(acc.x, acc.y);
    }
    if (tid < 16) {                           // cols 2048..2079 (counts + pad)
        int k = TTYPES * HDIM + tid * 2;
        float c0 = 0.f, c1 = 0.f;
        if (tid * 2 < TTYPES)
            c0 = (float)(rs2[v * TTYPES + tid * 2 + 1] - rs2[v * TTYPES + tid * 2]);
        if (tid * 2 + 1 < TTYPES)
            c1 = (float)(rs2[v * TTYPES + tid * 2 + 2] - rs2[v * TTYPES + tid * 2 + 1]);
        S[t_idx(v, k, KMSG)] = __floats2half2_rn(c0, c1);
    }
}

// ---------------- fp16 mma.sync GEMM (1 tile per CTA, 2 static jobs) ----------
#define STAGE_BYTES 16384
#define STAGE_H2    4096
#define GEMM_SMEM   (4 * STAGE_BYTES)

__global__ __launch_bounds__(128, 3) void gemm_f16_kernel(
    const __half2* __restrict__ A0, const __half2* __restrict__ B0,
    const float* __restrict__ bias0, float* __restrict__ C0f,
    __half2* __restrict__ C0h, __half2* __restrict__ C0hr,
    int K0, int N0, int nt0,
    const __half2* __restrict__ A1, const __half2* __restrict__ B1,
    const float* __restrict__ bias1, __half2* __restrict__ C1hr,
    int K1, int N1)
{
    extern __shared__ __half2 smh[];
    const int tid  = threadIdx.x;
    const int wid  = tid >> 5;
    const int lane = tid & 31;
    const int gid  = lane >> 2;
    const int tig  = lane & 3;
    const int wm   = wid >> 1;
    const int wn   = wid & 1;
    const uint32_t smb = smem_u32(smh);

    const int t = blockIdx.x;
    const __half2* At; const __half2* Bt; const float* bias;
    float* Cf; __half2* Ch; __half2* Chr; int K, N, br, cb;
    if (t < nt0) {
        At = A0; Bt = B0; bias = bias0; Cf = C0f; Ch = C0h; Chr = C0hr;
        K = K0; N = N0; br = t % 256; cb = t / 256;
    } else {
        int t1 = t - nt0;
        At = A1; Bt = B1; bias = bias1; Cf = (float*)0; Ch = (__half2*)0; Chr = C1hr;
        K = K1; N = N1; br = t1 % 256; cb = t1 / 256;
    }

    const int NC = K >> 5;
    const __half2* Apan = At + (size_t)(br * NC) * 2048;
    const __half2* Bpan = Bt + (size_t)(cb * NC) * 2048;

    float acc[4][8][4];
#pragma unroll
    for (int mt = 0; mt < 4; mt++)
#pragma unroll
        for (int nt = 0; nt < 8; nt++)
#pragma unroll
            for (int v = 0; v < 4; v++) acc[mt][nt][v] = 0.f;

    auto load_chunk = [&](int c) {
        uint32_t base = smb + (c & 3) * STAGE_BYTES;
        const char* ga = (const char*)(Apan + (size_t)c * 2048);
        const char* gb = (const char*)(Bpan + (size_t)c * 2048);
#pragma unroll
        for (int i = 0; i < 4; i++) {
            int off = tid * 16 + i * 2048;
            CP_ASYNC16(base + off, ga + off);
            CP_ASYNC16(base + 8192 + off, gb + off);
        }
        CP_COMMIT();
    };

    load_chunk(0);
    load_chunk(1);
    load_chunk(2);
    for (int c = 0; c < NC; c++) {
        if (c <= NC - 3)      { CP_WAIT2(); }
        else if (c == NC - 2) { CP_WAIT1(); }
        else                  { CP_WAIT0(); }
        __syncthreads();
        if (c + 3 < NC) load_chunk(c + 3);

        const __half2* Asb = smh + (c & 3) * STAGE_H2;
        const __half2* Bsb = Asb + 2048;
        const int swz = gid * 2;
#pragma unroll
        for (int step = 0; step < 2; step++) {
            const int kp0 = (step * 8 + tig) ^ swz;
            const int kp1 = (step * 8 + tig + 4) ^ swz;
            uint32_t af[4][4];
#pragma unroll
            for (int mt = 0; mt < 4; mt++) {
                int r0 = wm * 64 + mt * 16 + gid;
                af[mt][0] = *(const uint32_t*)&Asb[r0 * 16 + kp0];
                af[mt][1] = *(const uint32_t*)&Asb[(r0 + 8) * 16 + kp0];
                af[mt][2] = *(const uint32_t*)&Asb[r0 * 16 + kp1];
                af[mt][3] = *(const uint32_t*)&Asb[(r0 + 8) * 16 + kp1];
            }
            uint32_t bf[8][2];
#pragma unroll
            for (int nt = 0; nt < 8; nt++) {
                int cn = wn * 64 + nt * 8 + gid;
                bf[nt][0] = *(const uint32_t*)&Bsb[cn * 16 + kp0];
                bf[nt][1] = *(const uint32_t*)&Bsb[cn * 16 + kp1];
            }
#pragma unroll
            for (int mt = 0; mt < 4; mt++)
#pragma unroll
                for (int nt = 0; nt < 8; nt++)
                    mma_f16(acc[mt][nt], af[mt], bf[nt]);
        }
    }

    // epilogue
    const int col0 = cb * 128 + wn * 64;
#pragma unroll
    for (int mt = 0; mt < 4; mt++) {
        int rg = br * 128 + wm * 64 + mt * 16 + gid;
#pragma unroll
        for (int nt = 0; nt < 8; nt++) {
            int col = col0 + nt * 8 + tig * 2;
            float b0 = 0.f, b1 = 0.f;
            if (bias) { b0 = __ldg(&bias[col]); b1 = __ldg(&bias[col + 1]); }
            float2 v0 = make_float2(acc[mt][nt][0] + b0, acc[mt][nt][1] + b1);
            float2 v1 = make_float2(acc[mt][nt][2] + b0, acc[mt][nt][3] + b1);
            if (Cf) {
                *reinterpret_cast<float2*>(Cf + (size_t)rg * N + col) = v0;
                *reinterpret_cast<float2*>(Cf + (size_t)(rg + 8) * N + col) = v1;
            }
            if (Ch) {
                Ch[t_idx(rg, col, N)] = __floats2half2_rn(v0.x, v0.y);
                Ch[t_idx(rg + 8, col, N)] = __floats2half2_rn(v1.x, v1.y);
            }
            if (Chr) {
                Chr[((size_t)rg * N + col) >> 1] = __floats2half2_rn(v0.x, v0.y);
                Chr[((size_t)(rg + 8) * N + col) >> 1] = __floats2half2_rn(v1.x, v1.y);
            }
        }
    }
}

// ---------------- GRU elementwise (fp16 gi/gh; ht read+write in place) --------
__global__ void gru_kernel(const __half2* __restrict__ gi, const __half2* __restrict__ gh,
                           __half2* __restrict__ ht) {
    int idx = blockIdx.x * 256 + threadIdx.x;    // NNODES*64 total
    int n = idx >> 6;
    int d4 = (idx & 63) * 4;
    const __half2* gin = gi + (size_t)n * (3 * HDIM / 2);
    const __half2* ghn = gh + (size_t)n * (3 * HDIM / 2);
    int o0 = d4 >> 1;
    float2 ir0 = __half22float2(gin[o0]),                 ir1 = __half22float2(gin[o0 + 1]);
    float2 iz0 = __half22float2(gin[(HDIM >> 1) + o0]),   iz1 = __half22float2(gin[(HDIM >> 1) + o0 + 1]);
    float2 in0 = __half22float2(gin[HDIM + o0]),          in1 = __half22float2(gin[HDIM + o0 + 1]);
    float2 hr0 = __half22float2(ghn[o0]),                 hr1 = __half22float2(ghn[o0 + 1]);
    float2 hz0 = __half22float2(ghn[(HDIM >> 1) + o0]),   hz1 = __half22float2(ghn[(HDIM >> 1) + o0 + 1]);
    float2 hn0 = __half22float2(ghn[HDIM + o0]),          hn1 = __half22float2(ghn[HDIM + o0 + 1]);
    size_t i0 = t_idx(n, d4, HDIM);
    size_t i1 = t_idx(n, d4 + 2, HDIM);
    float2 hv0 = __half22float2(ht[i0]);
    float2 hv1 = __half22float2(ht[i1]);
    float4 o;
#define GRU1(X, IR, HR, IZ, HZ, IN, HN, HV) do { \
        float r = 1.f / (1.f + expf(-((IR) + (HR)))); \
        float z = 1.f / (1.f + expf(-((IZ) + (HZ)))); \
        float nn = tanhf((IN) + r * (HN)); \
        o.X = (1.f - z) * nn + z * (HV); \
    } while (0)
    GRU1(x, ir0.x, hr0.x, iz0.x, hz0.x, in0.x, hn0.x, hv0.x);
    GRU1(y, ir0.y, hr0.y, iz0.y, hz0.y, in0.y, hn0.y, hv0.y);
    GRU1(z, ir1.x, hr1.x, iz1.x, hz1.x, in1.x, hn1.x, hv1.x);
    GRU1(w, ir1.y, hr1.y, iz1.y, hz1.y, in1.y, hn1.y, hv1.y);
#undef GRU1
    ht[i0] = __floats2half2_rn(o.x, o.y);
    ht[i1] = __floats2half2_rn(o.z, o.w);
}

// ---------------- readout (two-pass, deterministic; reads fp16 tile) ----------
__global__ void readout_part_kernel(const __half2* __restrict__ ht, float* __restrict__ part) {
    int b = blockIdx.x;            // 0..31
    int c = blockIdx.y;            // 0..7
    int d = threadIdx.x;           // 0..255
    int n0 = b * MAXN_ + c * 128;  // 128-aligned
    size_t base = ((size_t)(n0 >> 7) * 8 + (d >> 5)) * 2048;
    int kq = (d & 31) >> 1;
    int hi = d & 1;
    float s = 0.f;
#pragma unroll 4
    for (int r = 0; r < 128; r++) {
        __half2 v = ht[base + r * 16 + (kq ^ ((r & 7) * 2))];
        s += hi ? __high2float(v) : __low2float(v);
    }
    part[(b * 8 + c) * HDIM + d] = s;
}
__global__ void readout_reduce_kernel(const float* __restrict__ part, float* __restrict__ out) {
    int b = blockIdx.x;
    int d = threadIdx.x;
    float s = 0.f;
#pragma unroll
    for (int c = 0; c < 8; c++) s += part[(b * 8 + c) * HDIM + d];
    out[b * HDIM + d] = s;
}

// ---------------- host orchestration -----------------------------------------
extern "C" void kernel_launch(void* const* d_in, const int* in_sizes, int n_in,
                              void* d_out, int out_size) {
    const float* node_features = (const float*)d_in[0];
    const int*   edge_index    = (const int*)  d_in[1];
    const int*   edge_type     = (const int*)  d_in[2];
    const float* Wp  = (const float*)d_in[3];
    const float* bp  = (const float*)d_in[4];
    const float* Wm  = (const float*)d_in[5];
    const float* bm  = (const float*)d_in[6];
    const float* Wih = (const float*)d_in[7];
    const float* Whh = (const float*)d_in[8];
    const float* bih = (const float*)d_in[9];
    const float* bhh = (const float*)d_in[10];
    float* out = (float*)d_out;

    const int* esrc = edge_index;
    const int* edst = edge_index + NEDGES;

    float *part;
    __half2 *gi, *gh, *Xp, *Wpp, *Wcat, *Wih_t, *Whh_t, *S, *m, *ht;
    int *deg, *rowstart, *deg8, *rs2, *cur2, *srcs;
    cudaGetSymbolAddress((void**)&gi,    g_gi);
    cudaGetSymbolAddress((void**)&gh,    g_gh);
    cudaGetSymbolAddress((void**)&part,  g_part);
    cudaGetSymbolAddress((void**)&Xp,    g_Xp);
    cudaGetSymbolAddress((void**)&Wpp,   g_Wpp);
    cudaGetSymbolAddress((void**)&Wcat,  g_Wcat);
    cudaGetSymbolAddress((void**)&Wih_t, g_Wih_t);
    cudaGetSymbolAddress((void**)&Whh_t, g_Whh_t);
    cudaGetSymbolAddress((void**)&S,     g_S);
    cudaGetSymbolAddress((void**)&m,     g_m);
    cudaGetSymbolAddress((void**)&ht,    g_ht);
    cudaGetSymbolAddress((void**)&deg,      g_deg);
    cudaGetSymbolAddress((void**)&rowstart, g_rowstart);
    cudaGetSymbolAddress((void**)&deg8,     g_deg8);
    cudaGetSymbolAddress((void**)&rs2,      g_rs2);
    cudaGetSymbolAddress((void**)&cur2,     g_cur2);
    cudaGetSymbolAddress((void**)&srcs,     g_srcs);

    cudaFuncSetAttribute(gemm_f16_kernel,
                         cudaFuncAttributeMaxDynamicSharedMemorySize, GEMM_SMEM);

    const int per_layer_wg = 3 * HDIM * (HDIM / 2);
    const int per_layer_wc = HDIM * (KMSG / 2);

    // prep (merged weight/input prep + type-segmented CSR; once per launch)
    cudaMemsetAsync(deg, 0, NNODES * sizeof(int));
    cudaMemsetAsync(deg8, 0, NNODES * TTYPES * sizeof(int));
    prep_all_kernel<<<(NPREP + 255) / 256, 256>>>(
        node_features, Wp, Wih, Whh, Wm, bm, Xp, Wpp, Wih_t, Whh_t, Wcat);
    // h0 -> ht only (fp16 tile); 512 tiles, single job
    gemm_f16_kernel<<<512, 128, GEMM_SMEM>>>(
        Xp, Wpp, bp, (float*)0, ht, (__half2*)0, FPAD, HDIM, 512,
        (const __half2*)0, (const __half2*)0, (const float*)0, (__half2*)0, 32, 128);
    hist_both_kernel<<<NEDGES / 256, 256>>>(edst, edge_type, deg, deg8);
    scan_kernel<<<1, 1024>>>(deg, rowstart);
    rs2_kernel<<<NNODES / 256, 256>>>(rowstart, deg8, rs2, cur2);
    scatter2_kernel<<<NEDGES / 256, 256>>>(esrc, edst, edge_type, cur2, srcs);

    for (int l = 0; l < LLAYERS; l++) {
        const __half2* Wc_l  = Wcat  + (size_t)l * per_layer_wc;
        const __half2* Wih_l = Wih_t + (size_t)l * per_layer_wg;
        const __half2* Whh_l = Whh_t + (size_t)l * per_layer_wg;
        const float*   bih_l = bih + (size_t)l * 3 * HDIM;
        const float*   bhh_l = bhh + (size_t)l * 3 * HDIM;

        aggregate_kernel<<<NNODES, 128>>>(ht, srcs, rs2, S);
        // merged static launch: tiles [0,512) = msg (K=2080, long, dispatched
        // first, fp16 tile out m), tiles [512,2048) = gh (K=256, fp16 rm out).
        gemm_f16_kernel<<<2048, 128, GEMM_SMEM>>>(
            S, Wc_l, (const float*)0, (float*)0, m, (__half2*)0,
            KMSG, HDIM, 512,
            ht, Whh_l, bhh_l, gh, HDIM, 3 * HDIM);
        // gi = m @ Wih_l^T + bih (1536 tiles, fp16 rm out)
        gemm_f16_kernel<<<1536, 128, GEMM_SMEM>>>(
            m, Wih_l, bih_l, (float*)0, (__half2*)0, gi,
            HDIM, 3 * HDIM, 1536,
            (const __half2*)0, (const __half2*)0, (const float*)0, (__half2*)0, 32, 128);

        gru_kernel<<<(NNODES * 64) / 256, 256>>>(gi, gh, ht);
    }

    readout_part_kernel<<<dim3(BGRAPH, 8), 256>>>(ht, part);
    readout_reduce_kernel<<<BGRAPH, HDIM>>>(part, out);
}